// round 9
// baseline (speedup 1.0000x reference)
#include <cuda_runtime.h>
#include <cstdint>
#include <cstddef>

// Shapes: B=1, H=12, S=384, V=64, D=768
// Outputs (fp32, concatenated): importance[384,384] @0, tv_norm[384,384] @147456,
// tv_std[384,384,768] @294912, resultant[384,768] @113541120

#define OFF_NORM 147456
#define OFF_TV   294912
#define OFF_RES  113541120u

// ---------------- device scratch (no allocations allowed) -------------------
__device__ __align__(16) float g_Tc[12*384*768];    // [h][s][d]
__device__ __align__(16) float g_At[384*4608];      // [k][h*384+s] = attn[h,k,s]
__device__ __align__(16) float g_hc[384*768];       // (hidden - mean_d)*w_ln
__device__ __align__(16) float g_resmn[384*768];    // eps - resultant
__device__ __align__(16) float g_part[8*384*768];   // split-K GEMM partials
__device__ __align__(16) float g_gram[384*96];      // per-s Gram of {Tc[h],hc}: 91 used
__device__ __align__(16) float g_biasc[768];        // (bias - mean)*w_ln
__device__ __align__(16) float g_inv[384];          // 1/std(pre_ln, ddof=1)

// (i,j) pairs for p=0..90 enumerating i<=j over 13 vectors
__device__ const signed char c_gi[91] = {
    0,0,0,0,0,0,0,0,0,0,0,0,0,
    1,1,1,1,1,1,1,1,1,1,1,1,
    2,2,2,2,2,2,2,2,2,2,2,
    3,3,3,3,3,3,3,3,3,3,
    4,4,4,4,4,4,4,4,4,
    5,5,5,5,5,5,5,5,
    6,6,6,6,6,6,6,
    7,7,7,7,7,7,
    8,8,8,8,8,
    9,9,9,9,
    10,10,10,
    11,11,
    12};
__device__ const signed char c_gj[91] = {
    0,1,2,3,4,5,6,7,8,9,10,11,12,
    1,2,3,4,5,6,7,8,9,10,11,12,
    2,3,4,5,6,7,8,9,10,11,12,
    3,4,5,6,7,8,9,10,11,12,
    4,5,6,7,8,9,10,11,12,
    5,6,7,8,9,10,11,12,
    6,7,8,9,10,11,12,
    7,8,9,10,11,12,
    8,9,10,11,12,
    9,10,11,12,
    10,11,12,
    11,12,
    12};

// ---------------- f32x2 helpers ---------------------------------------------
__device__ __forceinline__ unsigned long long pack2(float lo, float hi){
    unsigned long long r; asm("mov.b64 %0, {%1, %2};" : "=l"(r) : "f"(lo), "f"(hi)); return r;
}
__device__ __forceinline__ unsigned long long dup2(float a){
    unsigned long long r; asm("mov.b64 %0, {%1, %1};" : "=l"(r) : "f"(a)); return r;
}
__device__ __forceinline__ void unpack2(unsigned long long v, float& lo, float& hi){
    asm("mov.b64 {%0, %1}, %2;" : "=f"(lo), "=f"(hi) : "l"(v));
}
__device__ __forceinline__ void fma2(unsigned long long& acc, unsigned long long a, unsigned long long b){
    asm("fma.rn.f32x2 %0, %1, %2, %0;" : "+l"(acc) : "l"(a), "l"(b));
}
__device__ __forceinline__ unsigned long long add2(unsigned long long a, unsigned long long b){
    unsigned long long r; asm("add.rn.f32x2 %0, %1, %2;" : "=l"(r) : "l"(a), "l"(b)); return r;
}
__device__ __forceinline__ unsigned long long mul2(unsigned long long a, unsigned long long b){
    unsigned long long r; asm("mul.rn.f32x2 %0, %1, %2;" : "=l"(r) : "l"(a), "l"(b)); return r;
}

// ---------------- K1a: stats + attn-transpose --------------------------------
// blocks 0..384: row stats; blocks 385..768: At
__global__ __launch_bounds__(256) void k_prep_a(const float* __restrict__ preln,
                                                const float* __restrict__ hidden,
                                                const float* __restrict__ dbias,
                                                const float* __restrict__ wln,
                                                const float* __restrict__ attn){
    int bid = blockIdx.x, t = threadIdx.x;
    if (bid <= 384){
        __shared__ float w1[8], w2[8], sres[2];
        int lane = t & 31, wid = t >> 5;
        int b = bid;
        if (b < 384){
            const float* row = preln + (size_t)b*768;
            float s1=0.f, s2=0.f;
            for (int d=t; d<768; d+=256){ float x=row[d]; s1+=x; s2=fmaf(x,x,s2); }
            for (int o=16;o;o>>=1){ s1+=__shfl_xor_sync(~0u,s1,o); s2+=__shfl_xor_sync(~0u,s2,o); }
            if (lane==0){ w1[wid]=s1; w2[wid]=s2; }
            __syncthreads();
            if (t==0){
                float a=0.f,c=0.f;
                #pragma unroll
                for (int j=0;j<8;j++){ a+=w1[j]; c+=w2[j]; }
                float mean = a*(1.0f/768.0f);
                float var  = (c - a*mean)*(1.0f/767.0f);
                float inv  = rsqrtf(var);
                g_inv[b]=inv; sres[0]=inv;
            }
            __syncthreads();
            const float* hr = hidden + (size_t)b*768;
            float hs=0.f;
            for (int d=t; d<768; d+=256) hs += hr[d];
            for (int o=16;o;o>>=1) hs += __shfl_xor_sync(~0u,hs,o);
            __syncthreads();
            if (lane==0) w1[wid]=hs;
            __syncthreads();
            if (t==0){
                float a=0.f;
                #pragma unroll
                for (int j=0;j<8;j++) a+=w1[j];
                sres[1]=a*(1.0f/768.0f);
            }
            __syncthreads();
            float hmean = sres[1];
            for (int d=t; d<768; d+=256)
                g_hc[(size_t)b*768+d] = (hr[d]-hmean)*wln[d];
        } else {
            float s=0.f;
            for (int d=t; d<768; d+=256) s += dbias[d];
            for (int o=16;o;o>>=1) s += __shfl_xor_sync(~0u,s,o);
            if (lane==0) w1[wid]=s;
            __syncthreads();
            if (t==0){
                float a=0.f;
                #pragma unroll
                for (int j=0;j<8;j++) a+=w1[j];
                sres[0]=a*(1.0f/768.0f);
            }
            __syncthreads();
            float mean = sres[0];
            for (int d=t; d<768; d+=256) g_biasc[d] = (dbias[d]-mean)*wln[d];
        }
    } else {
        int k = bid - 385;
        float4* dst = (float4*)(g_At + (size_t)k*4608);
        for (int idx=t; idx<1152; idx+=256){
            int h = idx/96, j = idx - h*96;
            dst[h*96 + j] = ((const float4*)(attn + ((size_t)h*384 + k)*384))[j];
        }
    }
}

// ---------------- K1b: Tc[h][s][d] -------------------------------------------
__global__ __launch_bounds__(256) void k_prep_tc(const float* __restrict__ value,
                                                 const float* __restrict__ dw,
                                                 const float* __restrict__ wln){
    __shared__ __align__(16) float val[12*64];
    __shared__ __align__(16) float T[12*768];
    __shared__ float means[12];
    int i = blockIdx.x;          // 0..383
    int s0 = (i & 31)*12, h = i >> 5;
    int t = threadIdx.x;
    if (t < 192)
        ((float4*)val)[t] = ((const float4*)(value + ((size_t)h*384 + s0)*64))[t];
    __syncthreads();
    const unsigned long long* val2 = (const unsigned long long*)val;
    #pragma unroll 1
    for (int g=0; g<3; g++){
        int d = g*256 + t;
        unsigned long long w2r[32];
        const unsigned long long* wr = (const unsigned long long*)(dw + ((size_t)d*12 + h)*64);
        #pragma unroll
        for (int q=0;q<32;q++) w2r[q]=wr[q];
        #pragma unroll 1
        for (int s=0;s<12;s++){
            unsigned long long acc = 0ull;
            #pragma unroll
            for (int q=0;q<32;q++) fma2(acc, w2r[q], val2[s*32+q]);
            float lo,hi; unpack2(acc,lo,hi);
            T[s*768 + d] = lo + hi;
        }
    }
    __syncthreads();
    int w = t>>5, l = t&31;
    for (int s=w; s<12; s+=8){
        float sum=0.f;
        for (int q=l; q<768; q+=32) sum += T[s*768+q];
        #pragma unroll
        for (int o=16;o;o>>=1) sum += __shfl_xor_sync(~0u,sum,o);
        if (l==0) means[s] = sum*(1.0f/768.0f);
    }
    __syncthreads();
    #pragma unroll 1
    for (int g=0; g<3; g++){
        int d = g*256+t; float wl = wln[d];
        #pragma unroll
        for (int s=0;s<12;s++)
            g_Tc[((size_t)h*384 + s0 + s)*768 + d] = (T[s*768+d]-means[s])*wl;
    }
}

// ---------------- K2: per-s Gram of the 13 vectors {Tc[0..11], hc} ----------
__global__ __launch_bounds__(384) void k_gram(){
    __shared__ __align__(16) float V[13][768];
    int s = blockIdx.x, t = threadIdx.x;
    for (int idx=t; idx<13*768; idx+=384){
        int r = idx/768, d = idx - r*768;
        V[r][d] = (r<12) ? g_Tc[((size_t)r*384+s)*768+d] : g_hc[(size_t)s*768+d];
    }
    __syncthreads();
    int w = t>>5, lane = t&31;
    for (int p=w; p<91; p+=12){
        const float* vi = V[c_gi[p]];
        const float* vj = V[c_gj[p]];
        float acc=0.f;
        #pragma unroll 4
        for (int d=lane; d<768; d+=32) acc = fmaf(vi[d], vj[d], acc);
        #pragma unroll
        for (int o=16;o;o>>=1) acc += __shfl_xor_sync(~0u,acc,o);
        if (lane==0) g_gram[s*96+p] = acc;
    }
}

// ---------------- K3: split-K SGEMM  C[384,768] = At[384,4608] @ Tc ----------
__global__ __launch_bounds__(256, 2) void k_gemm(){
    __shared__ __align__(16) float As[16*132];
    __shared__ __align__(16) float Bs[16*128];
    int m0 = blockIdx.x*128, n0 = blockIdx.y*128, z = blockIdx.z;
    int K0 = z*576;
    int t = threadIdx.x;
    int ty = t>>4, tx = t&15;
    unsigned long long acc[8][4];
    #pragma unroll
    for (int i=0;i<8;i++)
        #pragma unroll
        for (int j=0;j<4;j++) acc[i][j]=0ull;
    for (int ks=0; ks<36; ks++){
        int kb = K0 + ks*16;
        #pragma unroll
        for (int rep=0; rep<2; rep++){
            int idx = t + rep*256;
            int r = idx>>2, c = (idx&3)*4;
            float4 a4 = *(const float4*)(g_At + (size_t)(m0+r)*4608 + kb + c);
            As[(c+0)*132+r]=a4.x; As[(c+1)*132+r]=a4.y;
            As[(c+2)*132+r]=a4.z; As[(c+3)*132+r]=a4.w;
            int rb = idx>>5, cb = (idx&31)*4;
            *(float4*)&Bs[rb*128+cb] = *(const float4*)(g_Tc + (size_t)(kb+rb)*768 + n0 + cb);
        }
        __syncthreads();
        #pragma unroll
        for (int kk=0; kk<16; kk++){
            float4 a1 = *(float4*)&As[kk*132 + ty*8];
            float4 a2 = *(float4*)&As[kk*132 + ty*8 + 4];
            float4 b1 = *(float4*)&Bs[kk*128 + tx*8];
            float4 b2 = *(float4*)&Bs[kk*128 + tx*8 + 4];
            unsigned long long bv0=pack2(b1.x,b1.y), bv1=pack2(b1.z,b1.w);
            unsigned long long bv2=pack2(b2.x,b2.y), bv3=pack2(b2.z,b2.w);
            float av[8]={a1.x,a1.y,a1.z,a1.w,a2.x,a2.y,a2.z,a2.w};
            #pragma unroll
            for (int i=0;i<8;i++){
                unsigned long long ad = dup2(av[i]);
                fma2(acc[i][0],ad,bv0); fma2(acc[i][1],ad,bv1);
                fma2(acc[i][2],ad,bv2); fma2(acc[i][3],ad,bv3);
            }
        }
        __syncthreads();
    }
    #pragma unroll
    for (int i=0;i<8;i++){
        int row = m0 + ty*8 + i;
        float* dst = g_part + ((size_t)z*384 + row)*768 + n0 + tx*8;
        ulonglong2 v0; v0.x=acc[i][0]; v0.y=acc[i][1];
        ulonglong2 v1; v1.x=acc[i][2]; v1.y=acc[i][3];
        *(ulonglong2*)dst = v0;
        *(ulonglong2*)(dst+4) = v1;
    }
}

// ---------------- K4: resultant + resmn --------------------------------------
__global__ void k_res(const float* __restrict__ lnb, float* __restrict__ out_res){
    int k = blockIdx.x;
    float inv = g_inv[k];
    for (int d=threadIdx.x; d<768; d+=256){
        float s = 0.f;
        #pragma unroll
        for (int z=0; z<8; z++) s += g_part[((size_t)z*384 + k)*768 + d];
        float ao = s + g_hc[(size_t)k*768 + d] + g_biasc[d];
        float r  = ao*inv + lnb[d];
        out_res[(size_t)k*768 + d] = r;
        g_resmn[(size_t)k*768 + d] = 1e-6f - r;
    }
}

// ---------------- K5: main fused kernel --------------------------------------
// block = (s, k-quarter of 96). 192 threads; thread owns 4 d for all 96 k.
// Mainloop: GEMV + tv_std store + abs-sum with 2-step butterfly.
// Tail: norm via Gram quadratic form (t<96) + abs-sum finish (t>=96).
__global__ __launch_bounds__(192) void k_main(const float* __restrict__ attn,
                                              float* __restrict__ out){
    __shared__ __align__(16) unsigned long long cs2[96*12];  // dup'd attn[h,k,s]*inv[k]
    __shared__ float pa[96][48];                             // abs partials [kk][w*8+lane]
    __shared__ float Gs[91];
    int s = blockIdx.x;
    int kbase = blockIdx.y*96;
    int t = threadIdx.x;

    // stage duplicated coefficients (1152 entries, 6 per thread)
    for (int idx=t; idx<1152; idx+=192){
        int kk = idx/12, h = idx - kk*12;
        int k = kbase + kk;
        float c = attn[(size_t)h*147456 + (size_t)k*384 + s] * g_inv[k];
        cs2[idx] = dup2(c);
    }
    if (t < 91) Gs[t] = g_gram[s*96 + t];

    int d0 = t*4;

    // register-resident Tc[h][d0..d0+3]
    unsigned long long tca[12], tcb[12];
    #pragma unroll
    for (int h=0; h<12; h++){
        ulonglong2 v = *(const ulonglong2*)(g_Tc + ((size_t)h*384 + s)*768 + d0);
        tca[h]=v.x; tcb[h]=v.y;
    }
    unsigned long long hca, hcb;
    {
        ulonglong2 v = *(const ulonglong2*)(g_hc + (size_t)s*768 + d0);
        unsigned long long iv = dup2(g_inv[s]);
        hca = mul2(v.x, iv); hcb = mul2(v.y, iv);
    }
    __syncthreads();

    int wid = t>>5, lane = t&31;
    float* out_tv = out + OFF_TV;

    // 4-deep prefetch ring for resmn rows
    ulonglong2 ring[4];
    #pragma unroll
    for (int p=0; p<4; p++)
        ring[p] = *(const ulonglong2*)(g_resmn + (size_t)(kbase+p)*768 + d0);

    #pragma unroll 2
    for (int kk=0; kk<96; kk++){
        int k = kbase + kk;
        ulonglong2 rv = ring[kk&3];
        if (kk+4 < 96)
            ring[kk&3] = *(const ulonglong2*)(g_resmn + (size_t)(k+4)*768 + d0);

        // 12 pre-duplicated coefficients: 6 x LDS.128 (broadcast)
        const ulonglong2* cp = (const ulonglong2*)&cs2[kk*12];
        ulonglong2 c01 = cp[0], c23 = cp[1], c45 = cp[2];
        ulonglong2 c67 = cp[3], c89 = cp[4], cAB = cp[5];
        unsigned long long cd[12] = { c01.x,c01.y, c23.x,c23.y, c45.x,c45.y,
                                      c67.x,c67.y, c89.x,c89.y, cAB.x,cAB.y };

        // split chains: two independent 6-FMA chains per half
        unsigned long long a0=0ull, a1=0ull, b0=0ull, b1=0ull;
        #pragma unroll
        for (int h=0; h<6; h++){
            fma2(a0, cd[h],   tca[h]);
            fma2(b0, cd[h],   tcb[h]);
            fma2(a1, cd[h+6], tca[h+6]);
            fma2(b1, cd[h+6], tcb[h+6]);
        }
        unsigned long long acc0 = add2(a0,a1);
        unsigned long long acc1 = add2(b0,b1);
        if (k==s){ acc0 = add2(acc0, hca); acc1 = add2(acc1, hcb); }

        // streaming store tv_std (16B per thread, warp-contiguous 512B)
        {
            float* dst = out_tv + ((size_t)k*384 + s)*768 + d0;
            asm volatile("st.global.cs.v2.u64 [%0], {%1, %2};"
                         :: "l"(dst), "l"(acc0), "l"(acc1) : "memory");
        }

        // |tv_std - resultant + eps| partial (abs folds into FADD operands)
        unsigned long long df0 = add2(acc0, rv.x);
        unsigned long long df1 = add2(acc1, rv.y);
        float x0,x1,x2,x3;
        unpack2(df0,x0,x1); unpack2(df1,x2,x3);
        float sa = (fabsf(x0)+fabsf(x1)) + (fabsf(x2)+fabsf(x3));
        // 2-step butterfly; lanes 0..7 hold 8 disjoint 4-lane sums
        sa += __shfl_xor_sync(~0u, sa, 16);
        sa += __shfl_xor_sync(~0u, sa, 8);
        if (lane < 8) pa[kk][wid*8 + lane] = sa;
    }
    __syncthreads();

    if (t < 96){
        // tv_norm via Gram quadratic form
        int kk = t, k = kbase + kk;
        float c[12];
        #pragma unroll
        for (int h=0; h<12; h++) c[h] = ((const float*)&cs2[kk*12+h])[0];
        float inv_s = g_inv[s];
        bool diag = (k==s);
        float acc = 0.f;
        int p = 0;
        #pragma unroll
        for (int i=0; i<12; i++){
            float ci = c[i];
            acc = fmaf(ci*ci, Gs[p], acc); p++;
            #pragma unroll
            for (int j=i+1; j<12; j++){ acc = fmaf(2.0f*ci*c[j], Gs[p], acc); p++; }
            if (diag) acc = fmaf(2.0f*inv_s*ci, Gs[p], acc);
            p++;
        }
        if (diag) acc = fmaf(inv_s*inv_s, Gs[90], acc);
        out[OFF_NORM + (size_t)k*384 + s] = sqrtf(fmaxf(acc, 0.f));
    } else {
        // importance: finish the abs-sum
        int kk = t - 96, k = kbase + kk;
        const float* buf = pa[kk];
        float v = 0.f;
        #pragma unroll
        for (int j=0; j<48; j++) v += buf[j];
        out[(size_t)k*384 + s] = -v;
    }
}

// ---------------- launch ------------------------------------------------------
extern "C" void kernel_launch(void* const* d_in, const int* in_sizes, int n_in,
                              void* d_out, int out_size){
    (void)in_sizes; (void)n_in; (void)out_size;
    const float* value  = (const float*)d_in[0];
    const float* attn   = (const float*)d_in[1];
    const float* hidden = (const float*)d_in[2];
    const float* preln  = (const float*)d_in[3];
    const float* dw     = (const float*)d_in[4];
    const float* dbias  = (const float*)d_in[5];
    const float* wln    = (const float*)d_in[6];
    const float* lnb    = (const float*)d_in[7];
    float* out = (float*)d_out;

    k_prep_a<<<769, 256>>>(preln, hidden, dbias, wln, attn);
    k_prep_tc<<<384, 256>>>(value, dw, wln);
    k_gram<<<384, 384>>>();
    k_gemm<<<dim3(3,6,8), 256>>>();     // 4th launch -> ncu captures this
    k_res<<<384, 256>>>(lnb, out + OFF_RES);
    k_main<<<dim3(384,4), 192>>>(attn, out);
}

// round 10
// speedup vs baseline: 1.0983x; 1.0983x over previous
#include <cuda_runtime.h>
#include <cstdint>
#include <cstddef>

// Shapes: B=1, H=12, S=384, V=64, D=768
// Outputs (fp32): importance[384,384] @0, tv_norm @147456, tv_std @294912, resultant @113541120

#define OFF_NORM 147456
#define OFF_TV   294912
#define OFF_RES  113541120u

// ---------------- device scratch ---------------------------------------------
__device__ __align__(16) float g_Tc[12*384*768];    // [h][s][d]
__device__ __align__(16) float g_Wt[768*768];       // Wt[j][d] = dw[d*768+j]
__device__ __align__(16) float g_ctx[384*768];      // [k][h*64+v]
__device__ __align__(16) float g_hc[384*768];       // (hidden - mean_d)*w_ln
__device__ __align__(16) float g_resmn[384*768];    // eps - resultant
__device__ __align__(16) float g_part[8*384*768];   // split-K proj partials
__device__ __align__(16) float g_gram[384*96];      // per-s Gram (91 used)
__device__ __align__(16) float g_mean[12*384];      // mean_d T[h,s,:]
__device__ __align__(16) float g_m2[12*384];        // sum_s attn[h,k,s]*mean[h,s]
__device__ __align__(16) float g_biasc[768];        // (bias - mean)*w_ln
__device__ __align__(16) float g_inv[384];          // 1/std(pre_ln, ddof=1)

// (i,j) pairs for p=0..90 enumerating i<=j over 13 vectors
__device__ const signed char c_gi[91] = {
    0,0,0,0,0,0,0,0,0,0,0,0,0, 1,1,1,1,1,1,1,1,1,1,1,1, 2,2,2,2,2,2,2,2,2,2,2,
    3,3,3,3,3,3,3,3,3,3, 4,4,4,4,4,4,4,4,4, 5,5,5,5,5,5,5,5, 6,6,6,6,6,6,6,
    7,7,7,7,7,7, 8,8,8,8,8, 9,9,9,9, 10,10,10, 11,11, 12};
__device__ const signed char c_gj[91] = {
    0,1,2,3,4,5,6,7,8,9,10,11,12, 1,2,3,4,5,6,7,8,9,10,11,12, 2,3,4,5,6,7,8,9,10,11,12,
    3,4,5,6,7,8,9,10,11,12, 4,5,6,7,8,9,10,11,12, 5,6,7,8,9,10,11,12, 6,7,8,9,10,11,12,
    7,8,9,10,11,12, 8,9,10,11,12, 9,10,11,12, 10,11,12, 11,12, 12};

// ---------------- f32x2 helpers ---------------------------------------------
__device__ __forceinline__ unsigned long long pack2(float lo, float hi){
    unsigned long long r; asm("mov.b64 %0, {%1, %2};" : "=l"(r) : "f"(lo), "f"(hi)); return r;
}
__device__ __forceinline__ unsigned long long dup2(float a){
    unsigned long long r; asm("mov.b64 %0, {%1, %1};" : "=l"(r) : "f"(a)); return r;
}
__device__ __forceinline__ void unpack2(unsigned long long v, float& lo, float& hi){
    asm("mov.b64 {%0, %1}, %2;" : "=f"(lo), "=f"(hi) : "l"(v));
}
__device__ __forceinline__ void fma2(unsigned long long& acc, unsigned long long a, unsigned long long b){
    asm("fma.rn.f32x2 %0, %1, %2, %0;" : "+l"(acc) : "l"(a), "l"(b));
}
__device__ __forceinline__ unsigned long long add2(unsigned long long a, unsigned long long b){
    unsigned long long r; asm("add.rn.f32x2 %0, %1, %2;" : "=l"(r) : "l"(a), "l"(b)); return r;
}
__device__ __forceinline__ unsigned long long mul2(unsigned long long a, unsigned long long b){
    unsigned long long r; asm("mul.rn.f32x2 %0, %1, %2;" : "=l"(r) : "l"(a), "l"(b)); return r;
}

// ---------------- K1a: stats + W transpose -----------------------------------
// blocks 0..384: row stats; blocks 385..960: 32x32 transpose tiles of dense_w
__global__ __launch_bounds__(256) void k_prep_a(const float* __restrict__ preln,
                                                const float* __restrict__ hidden,
                                                const float* __restrict__ dbias,
                                                const float* __restrict__ wln,
                                                const float* __restrict__ dw){
    int bid = blockIdx.x, t = threadIdx.x;
    if (bid <= 384){
        __shared__ float w1[8], w2[8], sres[2];
        int lane = t & 31, wid = t >> 5;
        int b = bid;
        if (b < 384){
            const float* row = preln + (size_t)b*768;
            float s1=0.f, s2=0.f;
            for (int d=t; d<768; d+=256){ float x=row[d]; s1+=x; s2=fmaf(x,x,s2); }
            for (int o=16;o;o>>=1){ s1+=__shfl_xor_sync(~0u,s1,o); s2+=__shfl_xor_sync(~0u,s2,o); }
            if (lane==0){ w1[wid]=s1; w2[wid]=s2; }
            __syncthreads();
            if (t==0){
                float a=0.f,c=0.f;
                #pragma unroll
                for (int j=0;j<8;j++){ a+=w1[j]; c+=w2[j]; }
                float mean = a*(1.0f/768.0f);
                float var  = (c - a*mean)*(1.0f/767.0f);
                float inv  = rsqrtf(var);
                g_inv[b]=inv; sres[0]=inv;
            }
            __syncthreads();
            const float* hr = hidden + (size_t)b*768;
            float hs=0.f;
            for (int d=t; d<768; d+=256) hs += hr[d];
            for (int o=16;o;o>>=1) hs += __shfl_xor_sync(~0u,hs,o);
            __syncthreads();
            if (lane==0) w1[wid]=hs;
            __syncthreads();
            if (t==0){
                float a=0.f;
                #pragma unroll
                for (int j=0;j<8;j++) a+=w1[j];
                sres[1]=a*(1.0f/768.0f);
            }
            __syncthreads();
            float hmean = sres[1];
            for (int d=t; d<768; d+=256)
                g_hc[(size_t)b*768+d] = (hr[d]-hmean)*wln[d];
        } else {
            float s=0.f;
            for (int d=t; d<768; d+=256) s += dbias[d];
            for (int o=16;o;o>>=1) s += __shfl_xor_sync(~0u,s,o);
            if (lane==0) w1[wid]=s;
            __syncthreads();
            if (t==0){
                float a=0.f;
                #pragma unroll
                for (int j=0;j<8;j++) a+=w1[j];
                sres[0]=a*(1.0f/768.0f);
            }
            __syncthreads();
            float mean = sres[0];
            for (int d=t; d<768; d+=256) g_biasc[d] = (dbias[d]-mean)*wln[d];
        }
    } else {
        // transpose: g_Wt[j][d] = dw[d*768 + j], 32x32 tiles
        __shared__ float tile[32][33];
        int tid = bid - 385;
        int tr = tid/24, tc = tid - tr*24;   // d-tile, j-tile
        int r = t>>5, c = t&31;
        #pragma unroll
        for (int rr=r; rr<32; rr+=8)
            tile[rr][c] = dw[(size_t)(tr*32+rr)*768 + tc*32 + c];
        __syncthreads();
        #pragma unroll
        for (int rr=r; rr<32; rr+=8)
            g_Wt[(size_t)(tc*32+rr)*768 + tr*32 + c] = tile[c][rr];
    }
}

// ---------------- K1b: Tc[h][s][d] + means ------------------------------------
__global__ __launch_bounds__(256) void k_prep_tc(const float* __restrict__ value,
                                                 const float* __restrict__ dw,
                                                 const float* __restrict__ wln){
    __shared__ __align__(16) float val[12*64];
    __shared__ __align__(16) float T[12*768];
    __shared__ float means[12];
    int i = blockIdx.x;          // 0..383
    int s0 = (i & 31)*12, h = i >> 5;
    int t = threadIdx.x;
    if (t < 192)
        ((float4*)val)[t] = ((const float4*)(value + ((size_t)h*384 + s0)*64))[t];
    __syncthreads();
    const unsigned long long* val2 = (const unsigned long long*)val;
    #pragma unroll 1
    for (int g=0; g<3; g++){
        int d = g*256 + t;
        unsigned long long w2r[32];
        const unsigned long long* wr = (const unsigned long long*)(dw + ((size_t)d*12 + h)*64);
        #pragma unroll
        for (int q=0;q<32;q++) w2r[q]=wr[q];
        #pragma unroll 1
        for (int s=0;s<12;s++){
            unsigned long long acc = 0ull;
            #pragma unroll
            for (int q=0;q<32;q++) fma2(acc, w2r[q], val2[s*32+q]);
            float lo,hi; unpack2(acc,lo,hi);
            T[s*768 + d] = lo + hi;
        }
    }
    __syncthreads();
    int w = t>>5, l = t&31;
    for (int s=w; s<12; s+=8){
        float sum=0.f;
        for (int q=l; q<768; q+=32) sum += T[s*768+q];
        #pragma unroll
        for (int o=16;o;o>>=1) sum += __shfl_xor_sync(~0u,sum,o);
        if (l==0){
            float m = sum*(1.0f/768.0f);
            means[s] = m;
            g_mean[h*384 + s0 + s] = m;
        }
    }
    __syncthreads();
    #pragma unroll 1
    for (int g=0; g<3; g++){
        int d = g*256+t; float wl = wln[d];
        #pragma unroll
        for (int s=0;s<12;s++)
            g_Tc[((size_t)h*384 + s0 + s)*768 + d] = (T[s*768+d]-means[s])*wl;
    }
}

// ---------------- K2: attention context  ctx[k][h*64+v] ----------------------
// block = (k-tile 32, head). thread = (k, 8 v). Also accumulates m2[h,k].
__global__ __launch_bounds__(256) void k_ctx(const float* __restrict__ attn,
                                             const float* __restrict__ value){
    __shared__ __align__(16) float As[32][68];
    __shared__ __align__(16) float Vs[64][64];
    __shared__ float Ms[64];
    int h = blockIdx.y, k0 = blockIdx.x*32;
    int t = threadIdx.x;
    int tk = t>>3, tv = (t&7)*8;
    unsigned long long acc[4] = {0ull,0ull,0ull,0ull};
    float m2 = 0.f;
    #pragma unroll 1
    for (int so=0; so<384; so+=64){
        #pragma unroll
        for (int rep=0; rep<2; rep++){
            int idx = t + rep*256;               // 0..511
            int r = idx>>4, c4 = (idx&15)*4;
            *(float4*)&As[r][c4] = *(const float4*)(attn + ((size_t)h*384 + k0+r)*384 + so + c4);
        }
        #pragma unroll
        for (int rep=0; rep<4; rep++){
            int idx = t + rep*256;               // 0..1023
            int r = idx>>4, c4 = (idx&15)*4;
            *(float4*)&Vs[r][c4] = *(const float4*)(value + ((size_t)h*384 + so+r)*64 + c4);
        }
        if (t < 64) Ms[t] = g_mean[h*384 + so + t];
        __syncthreads();
        #pragma unroll 4
        for (int s=0; s<64; s++){
            unsigned long long a = dup2(As[tk][s]);
            const unsigned long long* v2 = (const unsigned long long*)&Vs[s][tv];
            fma2(acc[0], a, v2[0]); fma2(acc[1], a, v2[1]);
            fma2(acc[2], a, v2[2]); fma2(acc[3], a, v2[3]);
        }
        if (t < 32){
            float mm=0.f;
            #pragma unroll 4
            for (int s=0;s<64;s++) mm = fmaf(As[t][s], Ms[s], mm);
            m2 += mm;
        }
        __syncthreads();
    }
    float* dst = g_ctx + (size_t)(k0+tk)*768 + h*64 + tv;
    ulonglong2 v0; v0.x=acc[0]; v0.y=acc[1];
    ulonglong2 v1; v1.x=acc[2]; v1.y=acc[3];
    *(ulonglong2*)dst = v0; *(ulonglong2*)(dst+4) = v1;
    if (t < 32) g_m2[h*384 + k0 + t] = m2;
}

// ---------------- K3: projection GEMM  proj[384,768] = ctx @ Wt --------------
// 128x128 tile, BK=16, split-K=8 (96 each), thread = 8m x 8n.
__global__ __launch_bounds__(256) void k_proj(){
    __shared__ __align__(16) float As[16*132];
    __shared__ __align__(16) float Bs[16*128];
    int m0 = blockIdx.x*128, n0 = blockIdx.y*128, z = blockIdx.z;
    int K0 = z*96;
    int t = threadIdx.x;
    int ty = t>>4, tx = t&15;
    unsigned long long acc[8][4];
    #pragma unroll
    for (int i=0;i<8;i++)
        #pragma unroll
        for (int j=0;j<4;j++) acc[i][j]=0ull;
    for (int ks=0; ks<6; ks++){
        int kb = K0 + ks*16;
        #pragma unroll
        for (int rep=0; rep<2; rep++){
            int idx = t + rep*256;
            int r = idx>>2, c = (idx&3)*4;
            float4 a4 = *(const float4*)(g_ctx + (size_t)(m0+r)*768 + kb + c);
            As[(c+0)*132+r]=a4.x; As[(c+1)*132+r]=a4.y;
            As[(c+2)*132+r]=a4.z; As[(c+3)*132+r]=a4.w;
            int rb = idx>>5, cb = (idx&31)*4;
            *(float4*)&Bs[rb*128+cb] = *(const float4*)(g_Wt + (size_t)(kb+rb)*768 + n0 + cb);
        }
        __syncthreads();
        #pragma unroll
        for (int kk=0; kk<16; kk++){
            float4 a1 = *(float4*)&As[kk*132 + ty*8];
            float4 a2 = *(float4*)&As[kk*132 + ty*8 + 4];
            float4 b1 = *(float4*)&Bs[kk*128 + tx*8];
            float4 b2 = *(float4*)&Bs[kk*128 + tx*8 + 4];
            unsigned long long bv0=pack2(b1.x,b1.y), bv1=pack2(b1.z,b1.w);
            unsigned long long bv2=pack2(b2.x,b2.y), bv3=pack2(b2.z,b2.w);
            float av[8]={a1.x,a1.y,a1.z,a1.w,a2.x,a2.y,a2.z,a2.w};
            #pragma unroll
            for (int i=0;i<8;i++){
                unsigned long long ad = dup2(av[i]);
                fma2(acc[i][0],ad,bv0); fma2(acc[i][1],ad,bv1);
                fma2(acc[i][2],ad,bv2); fma2(acc[i][3],ad,bv3);
            }
        }
        __syncthreads();
    }
    #pragma unroll
    for (int i=0;i<8;i++){
        int row = m0 + ty*8 + i;
        float* dst = g_part + ((size_t)z*384 + row)*768 + n0 + tx*8;
        ulonglong2 v0; v0.x=acc[i][0]; v0.y=acc[i][1];
        ulonglong2 v1; v1.x=acc[i][2]; v1.y=acc[i][3];
        *(ulonglong2*)dst = v0;
        *(ulonglong2*)(dst+4) = v1;
    }
}

// ---------------- K4: per-s Gram of the 13 vectors {Tc[0..11], hc} ----------
__global__ __launch_bounds__(384) void k_gram(){
    __shared__ __align__(16) float V[13][768];
    int s = blockIdx.x, t = threadIdx.x;
    for (int idx=t; idx<13*768; idx+=384){
        int r = idx/768, d = idx - r*768;
        V[r][d] = (r<12) ? g_Tc[((size_t)r*384+s)*768+d] : g_hc[(size_t)s*768+d];
    }
    __syncthreads();
    int w = t>>5, lane = t&31;
    for (int p=w; p<91; p+=12){
        const float* vi = V[c_gi[p]];
        const float* vj = V[c_gj[p]];
        float acc=0.f;
        #pragma unroll 4
        for (int d=lane; d<768; d+=32) acc = fmaf(vi[d], vj[d], acc);
        #pragma unroll
        for (int o=16;o;o>>=1) acc += __shfl_xor_sync(~0u,acc,o);
        if (lane==0) g_gram[s*96+p] = acc;
    }
}

// ---------------- K5: resultant + resmn --------------------------------------
__global__ void k_res(const float* __restrict__ lnb, const float* __restrict__ wln,
                      float* __restrict__ out_res){
    __shared__ float smm;
    int k = blockIdx.x;
    if (threadIdx.x==0){
        float m=0.f;
        #pragma unroll
        for (int h=0;h<12;h++) m += g_m2[h*384+k];
        smm = m;
    }
    __syncthreads();
    float mm = smm;
    float inv = g_inv[k];
    for (int d=threadIdx.x; d<768; d+=256){
        float s = 0.f;
        #pragma unroll
        for (int z=0; z<8; z++) s += g_part[((size_t)z*384 + k)*768 + d];
        float ao = (s - mm)*wln[d] + g_hc[(size_t)k*768 + d] + g_biasc[d];
        float r  = ao*inv + lnb[d];
        out_res[(size_t)k*768 + d] = r;
        g_resmn[(size_t)k*768 + d] = 1e-6f - r;
    }
}

// ---------------- K6: main fused kernel --------------------------------------
__global__ __launch_bounds__(192) void k_main(const float* __restrict__ attn,
                                              float* __restrict__ out){
    __shared__ __align__(16) unsigned long long cs2[96*12];  // dup'd attn[h,k,s]*inv[k]
    __shared__ float pa[96][24];                             // abs partials
    __shared__ float Gs[91];
    int s = blockIdx.x;
    int kbase = blockIdx.y*96;
    int t = threadIdx.x;

    for (int idx=t; idx<1152; idx+=192){
        int kk = idx/12, h = idx - kk*12;
        int k = kbase + kk;
        float c = attn[(size_t)h*147456 + (size_t)k*384 + s] * g_inv[k];
        cs2[idx] = dup2(c);
    }
    if (t < 91) Gs[t] = g_gram[s*96 + t];

    int d0 = t*4;

    unsigned long long tca[12], tcb[12];
    #pragma unroll
    for (int h=0; h<12; h++){
        ulonglong2 v = *(const ulonglong2*)(g_Tc + ((size_t)h*384 + s)*768 + d0);
        tca[h]=v.x; tcb[h]=v.y;
    }
    unsigned long long hca, hcb;
    {
        ulonglong2 v = *(const ulonglong2*)(g_hc + (size_t)s*768 + d0);
        unsigned long long iv = dup2(g_inv[s]);
        hca = mul2(v.x, iv); hcb = mul2(v.y, iv);
    }
    __syncthreads();

    int wid = t>>5, lane = t&31;
    float* out_tv = out + OFF_TV;

    ulonglong2 ring[4];
    #pragma unroll
    for (int p=0; p<4; p++)
        ring[p] = *(const ulonglong2*)(g_resmn + (size_t)(kbase+p)*768 + d0);

    #pragma unroll 2
    for (int kk=0; kk<96; kk++){
        int k = kbase + kk;
        ulonglong2 rv = ring[kk&3];
        if (kk+4 < 96)
            ring[kk&3] = *(const ulonglong2*)(g_resmn + (size_t)(k+4)*768 + d0);

        const ulonglong2* cp = (const ulonglong2*)&cs2[kk*12];
        ulonglong2 c01 = cp[0], c23 = cp[1], c45 = cp[2];
        ulonglong2 c67 = cp[3], c89 = cp[4], cAB = cp[5];
        unsigned long long cd[12] = { c01.x,c01.y, c23.x,c23.y, c45.x,c45.y,
                                      c67.x,c67.y, c89.x,c89.y, cAB.x,cAB.y };

        unsigned long long a0=0ull, a1=0ull, b0=0ull, b1=0ull;
        #pragma unroll
        for (int h=0; h<6; h++){
            fma2(a0, cd[h],   tca[h]);
            fma2(b0, cd[h],   tcb[h]);
            fma2(a1, cd[h+6], tca[h+6]);
            fma2(b1, cd[h+6], tcb[h+6]);
        }
        unsigned long long acc0 = add2(a0,a1);
        unsigned long long acc1 = add2(b0,b1);
        if (k==s){ acc0 = add2(acc0, hca); acc1 = add2(acc1, hcb); }

        {
            float* dst = out_tv + ((size_t)k*384 + s)*768 + d0;
            asm volatile("st.global.cs.v2.u64 [%0], {%1, %2};"
                         :: "l"(dst), "l"(acc0), "l"(acc1) : "memory");
        }

        unsigned long long df0 = add2(acc0, rv.x);
        unsigned long long df1 = add2(acc1, rv.y);
        float x0,x1,x2,x3;
        unpack2(df0,x0,x1); unpack2(df1,x2,x3);
        float sa = (fabsf(x0)+fabsf(x1)) + (fabsf(x2)+fabsf(x3));
        sa += __shfl_xor_sync(~0u, sa, 16);
        sa += __shfl_xor_sync(~0u, sa, 8);
        sa += __shfl_xor_sync(~0u, sa, 4);
        if (lane < 4) pa[kk][wid*4 + lane] = sa;
    }
    __syncthreads();

    if (t < 96){
        int kk = t, k = kbase + kk;
        float c[12];
        #pragma unroll
        for (int h=0; h<12; h++) c[h] = ((const float*)&cs2[kk*12+h])[0];
        float inv_s = g_inv[s];
        bool diag = (k==s);
        float acc = 0.f;
        int p = 0;
        #pragma unroll
        for (int i=0; i<12; i++){
            float ci = c[i];
            acc = fmaf(ci*ci, Gs[p], acc); p++;
            #pragma unroll
            for (int j=i+1; j<12; j++){ acc = fmaf(2.0f*ci*c[j], Gs[p], acc); p++; }
            if (diag) acc = fmaf(2.0f*inv_s*ci, Gs[p], acc);
            p++;
        }
        if (diag) acc = fmaf(inv_s*inv_s, Gs[90], acc);
        out[OFF_NORM + (size_t)k*384 + s] = sqrtf(fmaxf(acc, 0.f));
    } else {
        int kk = t - 96, k = kbase + kk;
        const float* buf = pa[kk];
        float v = 0.f;
        #pragma unroll
        for (int j=0; j<24; j++) v += buf[j];
        out[(size_t)k*384 + s] = -v;
    }
}

// ---------------- launch ------------------------------------------------------
extern "C" void kernel_launch(void* const* d_in, const int* in_sizes, int n_in,
                              void* d_out, int out_size){
    (void)in_sizes; (void)n_in; (void)out_size;
    const float* value  = (const float*)d_in[0];
    const float* attn   = (const float*)d_in[1];
    const float* hidden = (const float*)d_in[2];
    const float* preln  = (const float*)d_in[3];
    const float* dw     = (const float*)d_in[4];
    const float* dbias  = (const float*)d_in[5];
    const float* wln    = (const float*)d_in[6];
    const float* lnb    = (const float*)d_in[7];
    float* out = (float*)d_out;

    k_prep_a<<<961, 256>>>(preln, hidden, dbias, wln, dw);
    k_prep_tc<<<384, 256>>>(value, dw, wln);
    k_ctx<<<dim3(12,12), 256>>>(attn, value);
    k_proj<<<dim3(3,6,8), 256>>>();          // 4th launch -> profiled
    k_gram<<<384, 384>>>();
    k_res<<<384, 256>>>(lnb, wln, out + OFF_RES);
    k_main<<<dim3(384,4), 192>>>(attn, out);
}